// round 1
// baseline (speedup 1.0000x reference)
#include <cuda_runtime.h>
#include <cuda_bf16.h>
#include <math_constants.h>

// Problem constants (fixed shapes)
#define BATCH   2
#define SEQ     2048
#define NHEADS  16
#define DHEAD   128
#define DMODEL  2048            // NHEADS * DHEAD
#define DM3     6144            // 3 * DMODEL
#define MTOT    4096            // BATCH * SEQ

// Scratch (device globals; no allocation allowed)
__device__ float g_qkv[(size_t)MTOT * DM3];     // [B*S, 3*DMODEL]
__device__ float g_attn[(size_t)MTOT * DMODEL]; // [B*S, DMODEL]

// ---------------------------------------------------------------------------
// SGEMM 128x128x8, 8x8 per thread, bias fused. C[M,N] = A[M,K] @ B[K,N] + bias
// M,N multiples of 128; K multiple of 8 (all true here).
// ---------------------------------------------------------------------------
__global__ __launch_bounds__(256) void sgemm_bias_kernel(
    const float* __restrict__ A, const float* __restrict__ B,
    const float* __restrict__ bias, float* __restrict__ C,
    int M, int N, int K)
{
    __shared__ float As[8][128];
    __shared__ float Bs[8][128];

    const int tid = threadIdx.x;
    const int bm = blockIdx.y;
    const int bn = blockIdx.x;

    const float* Ab = A + (size_t)bm * 128 * K;
    const float* Bb = B + (size_t)bn * 128;

    const int arow = tid >> 1;          // 0..127
    const int acol = (tid & 1) * 4;     // 0 or 4
    const int brow = tid >> 5;          // 0..7
    const int bcol = (tid & 31) * 4;    // 0..124

    const int ty = tid >> 4;            // 0..15
    const int tx = tid & 15;            // 0..15

    float acc[8][8];
    #pragma unroll
    for (int m = 0; m < 8; m++)
        #pragma unroll
        for (int n = 0; n < 8; n++) acc[m][n] = 0.f;

    for (int k0 = 0; k0 < K; k0 += 8) {
        float4 a = *(const float4*)(Ab + (size_t)arow * K + k0 + acol);
        As[acol + 0][arow] = a.x;
        As[acol + 1][arow] = a.y;
        As[acol + 2][arow] = a.z;
        As[acol + 3][arow] = a.w;
        float4 bv = *(const float4*)(Bb + (size_t)(k0 + brow) * N + bcol);
        *(float4*)(&Bs[brow][bcol]) = bv;
        __syncthreads();

        #pragma unroll
        for (int k = 0; k < 8; k++) {
            float ra[8], rb[8];
            #pragma unroll
            for (int m = 0; m < 8; m++) ra[m] = As[k][ty * 8 + m];
            #pragma unroll
            for (int n = 0; n < 8; n++) rb[n] = Bs[k][tx * 8 + n];
            #pragma unroll
            for (int m = 0; m < 8; m++)
                #pragma unroll
                for (int n = 0; n < 8; n++) acc[m][n] += ra[m] * rb[n];
        }
        __syncthreads();
    }

    float* Cb = C + (size_t)(bm * 128 + ty * 8) * N + bn * 128 + tx * 8;
    const float* biasb = bias + bn * 128 + tx * 8;
    float bn4[8];
    #pragma unroll
    for (int n = 0; n < 8; n++) bn4[n] = biasb[n];
    #pragma unroll
    for (int m = 0; m < 8; m++) {
        float4 w0, w1;
        w0.x = acc[m][0] + bn4[0]; w0.y = acc[m][1] + bn4[1];
        w0.z = acc[m][2] + bn4[2]; w0.w = acc[m][3] + bn4[3];
        w1.x = acc[m][4] + bn4[4]; w1.y = acc[m][5] + bn4[5];
        w1.z = acc[m][6] + bn4[6]; w1.w = acc[m][7] + bn4[7];
        *(float4*)(Cb + (size_t)m * N + 0) = w0;
        *(float4*)(Cb + (size_t)m * N + 4) = w1;
    }
}

// ---------------------------------------------------------------------------
// Flash attention (causal), fp32.
// Grid: (S/32, NHEADS, BATCH), 128 threads.
// Thread (r = tid>>2, cg = tid&3): row r of the 32-row q tile, d-slice =
// float4 words {cg, cg+4, ..., cg+28} (interleaved -> conflict-free LDS).
// qkv layout: [B*S, 6144] with Q at col h*128, K at 2048 + h*128, V at 4096 + h*128.
// ---------------------------------------------------------------------------
__global__ __launch_bounds__(128) void flash_attn_kernel(
    const float* __restrict__ qkv, float* __restrict__ out)
{
    const int qblk = blockIdx.x;     // 0..63
    const int h    = blockIdx.y;
    const int b    = blockIdx.z;
    const int tid  = threadIdx.x;
    const int r    = tid >> 2;       // 0..31
    const int cg   = tid & 3;        // 0..3

    __shared__ float4 Ks[32][32];
    __shared__ float4 Vs[32][32];

    const int q_idx = qblk * 32 + r;
    const float* qbase = qkv + (size_t)(b * SEQ + q_idx) * DM3 + h * DHEAD;

    float4 q4[8];
    #pragma unroll
    for (int t = 0; t < 8; t++)
        q4[t] = *(const float4*)(qbase + (cg + 4 * t) * 4);

    float m = -CUDART_INF_F;
    float l = 0.f;
    float4 o4[8];
    #pragma unroll
    for (int t = 0; t < 8; t++) o4[t] = make_float4(0.f, 0.f, 0.f, 0.f);

    const float scale = 0.08838834764831845f;  // 1/sqrt(128)
    const int ntiles = qblk + 1;

    for (int kt = 0; kt < ntiles; kt++) {
        // Stage K,V tile (rows kt*32 .. +31) into shared, interleaved words.
        {
            const float* kbase = qkv + (size_t)(b * SEQ + kt * 32 + r) * DM3
                                 + h * DHEAD + DMODEL;      // K block
            const float* vbase = kbase + DMODEL;            // V block
            #pragma unroll
            for (int u = 0; u < 8; u++) {
                Ks[r][cg + 4 * u] = *(const float4*)(kbase + (cg + 4 * u) * 4);
                Vs[r][cg + 4 * u] = *(const float4*)(vbase + (cg + 4 * u) * 4);
            }
        }
        __syncthreads();

        const bool diag = (kt == qblk);
        float sv[32];
        float mt = -CUDART_INF_F;
        #pragma unroll
        for (int j = 0; j < 32; j++) {
            float acc = 0.f;
            #pragma unroll
            for (int t = 0; t < 8; t++) {
                float4 kk = Ks[j][cg + 4 * t];
                acc += q4[t].x * kk.x + q4[t].y * kk.y
                     + q4[t].z * kk.z + q4[t].w * kk.w;
            }
            acc += __shfl_xor_sync(0xffffffffu, acc, 1);
            acc += __shfl_xor_sync(0xffffffffu, acc, 2);
            acc *= scale;
            if (diag && j > r) acc = -CUDART_INF_F;
            sv[j] = acc;
            mt = fmaxf(mt, acc);
        }

        const float m_new = fmaxf(m, mt);
        const float corr = __expf(m - m_new);   // 0 on first tile (m = -inf)
        l *= corr;
        #pragma unroll
        for (int t = 0; t < 8; t++) {
            o4[t].x *= corr; o4[t].y *= corr;
            o4[t].z *= corr; o4[t].w *= corr;
        }
        #pragma unroll
        for (int j = 0; j < 32; j++) {
            float p = __expf(sv[j] - m_new);
            l += p;
            #pragma unroll
            for (int t = 0; t < 8; t++) {
                float4 vv = Vs[j][cg + 4 * t];
                o4[t].x += p * vv.x; o4[t].y += p * vv.y;
                o4[t].z += p * vv.z; o4[t].w += p * vv.w;
            }
        }
        m = m_new;
        __syncthreads();
    }

    const float inv = 1.f / l;
    float* obase = out + (size_t)(b * SEQ + q_idx) * DMODEL + h * DHEAD;
    #pragma unroll
    for (int t = 0; t < 8; t++) {
        float4 w = o4[t];
        w.x *= inv; w.y *= inv; w.z *= inv; w.w *= inv;
        *(float4*)(obase + (cg + 4 * t) * 4) = w;
    }
}

// ---------------------------------------------------------------------------
// kernel_launch
// Inputs (metadata order): x [B,S,2048] f32, W_qkv [2048,6144] f32,
// b_qkv [6144] f32, W_out [2048,2048] f32, b_out [2048] f32.
// Output: [B,S,2048] f32.
// ---------------------------------------------------------------------------
extern "C" void kernel_launch(void* const* d_in, const int* in_sizes, int n_in,
                              void* d_out, int out_size)
{
    const float* x     = (const float*)d_in[0];
    const float* W_qkv = (const float*)d_in[1];
    const float* b_qkv = (const float*)d_in[2];
    const float* W_out = (const float*)d_in[3];
    const float* b_out = (const float*)d_in[4];
    float* out = (float*)d_out;

    float* qkv;
    float* attn;
    cudaGetSymbolAddress((void**)&qkv, g_qkv);
    cudaGetSymbolAddress((void**)&attn, g_attn);

    // 1) QKV GEMM: [4096,2048] @ [2048,6144] + b -> g_qkv
    sgemm_bias_kernel<<<dim3(DM3 / 128, MTOT / 128), 256>>>(
        x, W_qkv, b_qkv, qkv, MTOT, DM3, DMODEL);

    // 2) Causal flash attention -> g_attn ([B*S, 2048], heads interleaved)
    flash_attn_kernel<<<dim3(SEQ / 32, NHEADS, BATCH), 128>>>(qkv, attn);

    // 3) Output GEMM: [4096,2048] @ [2048,2048] + b -> out
    sgemm_bias_kernel<<<dim3(DMODEL / 128, MTOT / 128), 256>>>(
        attn, W_out, b_out, out, MTOT, DMODEL, DMODEL);
}

// round 2
// speedup vs baseline: 1.3422x; 1.3422x over previous
#include <cuda_runtime.h>
#include <cuda_bf16.h>
#include <math_constants.h>

// Problem constants (fixed shapes)
#define BATCH   2
#define SEQ     2048
#define NHEADS  16
#define DHEAD   128
#define DMODEL  2048            // NHEADS * DHEAD
#define DM3     6144            // 3 * DMODEL
#define MTOT    4096            // BATCH * SEQ

// Scratch (device globals; no allocation allowed)
__device__ float g_qkv[(size_t)MTOT * DM3];     // [B*S, 3*DMODEL]
__device__ float g_attn[(size_t)MTOT * DMODEL]; // [B*S, DMODEL]

// ---------------------------------------------------------------------------
// Tensor-core GEMM with bf16 triple-K decomposition (near-fp32 accuracy).
// C[M,N] = A[M,K] @ B[K,N] + bias.  A,B,C fp32 row-major.
// Each original k is expanded to 3 bf16 slots:
//   A' = (a_hi, a_lo, a_hi),  B' = (b_hi, b_hi, b_lo)
// so sum over expanded K = a_hi*b_hi + a_lo*b_hi + a_hi*b_lo  (error ~2^-16).
//
// Block tile 128x128, K-tile 16 (-> 48 bf16), 256 threads = 8 warps (4m x 2n),
// warp tile 32x64 -> per k16 step: 2 A-frags, 8 B-frags, 16 mma.m16n8k16.
// Smem: A [m][k'] and B [n][k'] (both K-contiguous), row stride 28 words
// (24 data + 4 pad) -> all fragment LDS.32 are bank-conflict-free.
// ---------------------------------------------------------------------------

static __device__ __forceinline__ unsigned int bf_hi(float x) {
    __nv_bfloat16 h = __float2bfloat16(x);           // round-to-nearest
    return (unsigned int)*reinterpret_cast<unsigned short*>(&h);
}
static __device__ __forceinline__ void bf_split(float x, unsigned int& h, unsigned int& l, float& hf) {
    __nv_bfloat16 hb = __float2bfloat16(x);
    hf = __bfloat162float(hb);
    h = (unsigned int)*reinterpret_cast<unsigned short*>(&hb);
    __nv_bfloat16 lb = __float2bfloat16(x - hf);
    l = (unsigned int)*reinterpret_cast<unsigned short*>(&lb);
}

// Pack two consecutive-k source floats into 3 expanded words.
// A pattern per k: [hi, lo, hi]  -> words (hi0,lo0) (hi0,hi1) (lo1,hi1)
static __device__ __forceinline__ void pack3_A(unsigned int* p, float x0, float x1) {
    unsigned int h0, l0, h1, l1; float f;
    bf_split(x0, h0, l0, f);
    bf_split(x1, h1, l1, f);
    p[0] = h0 | (l0 << 16);
    p[1] = h0 | (h1 << 16);
    p[2] = l1 | (h1 << 16);
}
// B pattern per k: [hi, hi, lo]  -> words (hi0,hi0) (lo0,hi1) (hi1,lo1)
static __device__ __forceinline__ void pack3_B(unsigned int* p, float x0, float x1) {
    unsigned int h0, l0, h1, l1; float f;
    bf_split(x0, h0, l0, f);
    bf_split(x1, h1, l1, f);
    p[0] = h0 | (h0 << 16);
    p[1] = l0 | (h1 << 16);
    p[2] = h1 | (l1 << 16);
}

static __device__ __forceinline__ void mma_bf16(
    float& c0, float& c1, float& c2, float& c3,
    unsigned int a0, unsigned int a1, unsigned int a2, unsigned int a3,
    unsigned int b0, unsigned int b1)
{
    asm volatile(
        "mma.sync.aligned.m16n8k16.row.col.f32.bf16.bf16.f32 "
        "{%0,%1,%2,%3}, {%4,%5,%6,%7}, {%8,%9}, {%0,%1,%2,%3};\n"
        : "+f"(c0), "+f"(c1), "+f"(c2), "+f"(c3)
        : "r"(a0), "r"(a1), "r"(a2), "r"(a3), "r"(b0), "r"(b1));
}

#define WSTRIDE 28   // words per smem row (24 data + 4 pad)

__global__ __launch_bounds__(256) void gemm_tc_bias_kernel(
    const float* __restrict__ A, const float* __restrict__ B,
    const float* __restrict__ bias, float* __restrict__ C,
    int M, int N, int K)
{
    __shared__ unsigned int As32[128 * WSTRIDE];
    __shared__ unsigned int Bs32[128 * WSTRIDE];

    const int t    = threadIdx.x;
    const int bm   = blockIdx.y;
    const int bn   = blockIdx.x;
    const int wid  = t >> 5;
    const int lane = t & 31;
    const int warp_m = wid >> 1;    // 0..3
    const int warp_n = wid & 1;     // 0..1
    const int g = lane >> 2;        // 0..7
    const int q = lane & 3;         // 0..3

    // Fill assignments
    const int aRow = t >> 2;            // 0..63 (and +64)
    const int aK4  = (t & 3) * 4;       // 0,4,8,12
    const int bK2  = 2 * (t >> 5);      // 0,2,...,14
    const int bN0  = t & 31;            // 0..31 (cols bN0+32j)

    const float* Abase = A + (size_t)(bm * 128 + aRow) * K + aK4;
    const float* Bbase = B + (size_t)bK2 * N + bn * 128 + bN0;

    float c[2][8][4];
    #pragma unroll
    for (int mf = 0; mf < 2; mf++)
        #pragma unroll
        for (int nf = 0; nf < 8; nf++)
            #pragma unroll
            for (int i = 0; i < 4; i++) c[mf][nf][i] = 0.f;

    const int nK = K / 16;

    // Prefetch tile 0
    float4 pa0 = *(const float4*)(Abase);
    float4 pa1 = *(const float4*)(Abase + (size_t)64 * K);
    float  pb[8];
    #pragma unroll
    for (int j = 0; j < 4; j++) {
        pb[2 * j + 0] = Bbase[(size_t)0 * N + 32 * j];
        pb[2 * j + 1] = Bbase[(size_t)1 * N + 32 * j];
    }

    for (int kt = 0; kt < nK; kt++) {
        __syncthreads();
        // Store expanded tile to smem
        pack3_A(&As32[aRow * WSTRIDE + 6 * (t & 3) + 0], pa0.x, pa0.y);
        pack3_A(&As32[aRow * WSTRIDE + 6 * (t & 3) + 3], pa0.z, pa0.w);
        pack3_A(&As32[(aRow + 64) * WSTRIDE + 6 * (t & 3) + 0], pa1.x, pa1.y);
        pack3_A(&As32[(aRow + 64) * WSTRIDE + 6 * (t & 3) + 3], pa1.z, pa1.w);
        #pragma unroll
        for (int j = 0; j < 4; j++)
            pack3_B(&Bs32[(bN0 + 32 * j) * WSTRIDE + 3 * (t >> 5)],
                    pb[2 * j + 0], pb[2 * j + 1]);
        __syncthreads();

        // Prefetch next tile
        if (kt + 1 < nK) {
            const float* An = Abase + (kt + 1) * 16;
            pa0 = *(const float4*)(An);
            pa1 = *(const float4*)(An + (size_t)64 * K);
            const float* Bn = Bbase + (size_t)(kt + 1) * 16 * N;
            #pragma unroll
            for (int j = 0; j < 4; j++) {
                pb[2 * j + 0] = Bn[(size_t)0 * N + 32 * j];
                pb[2 * j + 1] = Bn[(size_t)1 * N + 32 * j];
            }
        }

        // Compute: 3 k16 steps over the expanded 48-wide tile
        #pragma unroll
        for (int s = 0; s < 3; s++) {
            unsigned int af[2][4];
            #pragma unroll
            for (int mf = 0; mf < 2; mf++) {
                const int mrow = warp_m * 32 + mf * 16 + g;
                const int idx = mrow * WSTRIDE + 8 * s + q;
                af[mf][0] = As32[idx];
                af[mf][1] = As32[idx + 8 * WSTRIDE];
                af[mf][2] = As32[idx + 4];
                af[mf][3] = As32[idx + 8 * WSTRIDE + 4];
            }
            #pragma unroll
            for (int nf = 0; nf < 8; nf++) {
                const int nrow = warp_n * 64 + nf * 8 + g;
                const int idx = nrow * WSTRIDE + 8 * s + q;
                unsigned int b0 = Bs32[idx];
                unsigned int b1 = Bs32[idx + 4];
                mma_bf16(c[0][nf][0], c[0][nf][1], c[0][nf][2], c[0][nf][3],
                         af[0][0], af[0][1], af[0][2], af[0][3], b0, b1);
                mma_bf16(c[1][nf][0], c[1][nf][1], c[1][nf][2], c[1][nf][3],
                         af[1][0], af[1][1], af[1][2], af[1][3], b0, b1);
            }
        }
    }

    // Epilogue: bias + store (float2, 8B aligned since col = ... + 2q)
    const int crow0 = bm * 128 + warp_m * 32 + g;
    const int ccol0 = bn * 128 + warp_n * 64 + 2 * q;
    #pragma unroll
    for (int nf = 0; nf < 8; nf++) {
        const int col = ccol0 + nf * 8;
        const float bx = bias[col];
        const float by = bias[col + 1];
        #pragma unroll
        for (int mf = 0; mf < 2; mf++) {
            const int row = crow0 + mf * 16;
            float2 w0 = make_float2(c[mf][nf][0] + bx, c[mf][nf][1] + by);
            float2 w1 = make_float2(c[mf][nf][2] + bx, c[mf][nf][3] + by);
            *(float2*)(C + (size_t)row * N + col) = w0;
            *(float2*)(C + (size_t)(row + 8) * N + col) = w1;
        }
    }
}

// ---------------------------------------------------------------------------
// Flash attention (causal), fp32. Unchanged from round 1.
// Grid: (S/32, NHEADS, BATCH), 128 threads.
// ---------------------------------------------------------------------------
__global__ __launch_bounds__(128) void flash_attn_kernel(
    const float* __restrict__ qkv, float* __restrict__ out)
{
    const int qblk = blockIdx.x;     // 0..63
    const int h    = blockIdx.y;
    const int b    = blockIdx.z;
    const int tid  = threadIdx.x;
    const int r    = tid >> 2;       // 0..31
    const int cg   = tid & 3;        // 0..3

    __shared__ float4 Ks[32][32];
    __shared__ float4 Vs[32][32];

    const int q_idx = qblk * 32 + r;
    const float* qbase = qkv + (size_t)(b * SEQ + q_idx) * DM3 + h * DHEAD;

    float4 q4[8];
    #pragma unroll
    for (int t = 0; t < 8; t++)
        q4[t] = *(const float4*)(qbase + (cg + 4 * t) * 4);

    float m = -CUDART_INF_F;
    float l = 0.f;
    float4 o4[8];
    #pragma unroll
    for (int t = 0; t < 8; t++) o4[t] = make_float4(0.f, 0.f, 0.f, 0.f);

    const float scale = 0.08838834764831845f;  // 1/sqrt(128)
    const int ntiles = qblk + 1;

    for (int kt = 0; kt < ntiles; kt++) {
        {
            const float* kbase = qkv + (size_t)(b * SEQ + kt * 32 + r) * DM3
                                 + h * DHEAD + DMODEL;      // K block
            const float* vbase = kbase + DMODEL;            // V block
            #pragma unroll
            for (int u = 0; u < 8; u++) {
                Ks[r][cg + 4 * u] = *(const float4*)(kbase + (cg + 4 * u) * 4);
                Vs[r][cg + 4 * u] = *(const float4*)(vbase + (cg + 4 * u) * 4);
            }
        }
        __syncthreads();

        const bool diag = (kt == qblk);
        float sv[32];
        float mt = -CUDART_INF_F;
        #pragma unroll
        for (int j = 0; j < 32; j++) {
            float acc = 0.f;
            #pragma unroll
            for (int t = 0; t < 8; t++) {
                float4 kk = Ks[j][cg + 4 * t];
                acc += q4[t].x * kk.x + q4[t].y * kk.y
                     + q4[t].z * kk.z + q4[t].w * kk.w;
            }
            acc += __shfl_xor_sync(0xffffffffu, acc, 1);
            acc += __shfl_xor_sync(0xffffffffu, acc, 2);
            acc *= scale;
            if (diag && j > r) acc = -CUDART_INF_F;
            sv[j] = acc;
            mt = fmaxf(mt, acc);
        }

        const float m_new = fmaxf(m, mt);
        const float corr = __expf(m - m_new);
        l *= corr;
        #pragma unroll
        for (int t = 0; t < 8; t++) {
            o4[t].x *= corr; o4[t].y *= corr;
            o4[t].z *= corr; o4[t].w *= corr;
        }
        #pragma unroll
        for (int j = 0; j < 32; j++) {
            float p = __expf(sv[j] - m_new);
            l += p;
            #pragma unroll
            for (int t = 0; t < 8; t++) {
                float4 vv = Vs[j][cg + 4 * t];
                o4[t].x += p * vv.x; o4[t].y += p * vv.y;
                o4[t].z += p * vv.z; o4[t].w += p * vv.w;
            }
        }
        m = m_new;
        __syncthreads();
    }

    const float inv = 1.f / l;
    float* obase = out + (size_t)(b * SEQ + q_idx) * DMODEL + h * DHEAD;
    #pragma unroll
    for (int t = 0; t < 8; t++) {
        float4 w = o4[t];
        w.x *= inv; w.y *= inv; w.z *= inv; w.w *= inv;
        *(float4*)(obase + (cg + 4 * t) * 4) = w;
    }
}

// ---------------------------------------------------------------------------
// kernel_launch
// Inputs: x [B,S,2048] f32, W_qkv [2048,6144] f32, b_qkv [6144] f32,
//         W_out [2048,2048] f32, b_out [2048] f32.  Output: [B,S,2048] f32.
// ---------------------------------------------------------------------------
extern "C" void kernel_launch(void* const* d_in, const int* in_sizes, int n_in,
                              void* d_out, int out_size)
{
    const float* x     = (const float*)d_in[0];
    const float* W_qkv = (const float*)d_in[1];
    const float* b_qkv = (const float*)d_in[2];
    const float* W_out = (const float*)d_in[3];
    const float* b_out = (const float*)d_in[4];
    float* out = (float*)d_out;

    float* qkv;
    float* attn;
    cudaGetSymbolAddress((void**)&qkv, g_qkv);
    cudaGetSymbolAddress((void**)&attn, g_attn);

    // 1) QKV GEMM: [4096,2048] @ [2048,6144] + b -> g_qkv
    gemm_tc_bias_kernel<<<dim3(DM3 / 128, MTOT / 128), 256>>>(
        x, W_qkv, b_qkv, qkv, MTOT, DM3, DMODEL);

    // 2) Causal flash attention -> g_attn ([B*S, 2048], heads interleaved)
    flash_attn_kernel<<<dim3(SEQ / 32, NHEADS, BATCH), 128>>>(qkv, attn);

    // 3) Output GEMM: [4096,2048] @ [2048,2048] + b -> out
    gemm_tc_bias_kernel<<<dim3(DMODEL / 128, MTOT / 128), 256>>>(
        attn, W_out, b_out, out, MTOT, DMODEL, DMODEL);
}

// round 3
// speedup vs baseline: 2.4409x; 1.8185x over previous
#include <cuda_runtime.h>
#include <cuda_bf16.h>
#include <math_constants.h>

// Problem constants (fixed shapes)
#define BATCH   2
#define SEQ     2048
#define NHEADS  16
#define DHEAD   128
#define DMODEL  2048
#define DM3     6144
#define MTOT    4096

__device__ float g_qkv[(size_t)MTOT * DM3];
__device__ float g_attn[(size_t)MTOT * DMODEL];

// ---------------------------------------------------------------------------
// Common helpers
// ---------------------------------------------------------------------------
static __device__ __forceinline__ void bf_split(float x, unsigned int& h, unsigned int& l, float& hf) {
    __nv_bfloat16 hb = __float2bfloat16(x);
    hf = __bfloat162float(hb);
    h = (unsigned int)*reinterpret_cast<unsigned short*>(&hb);
    __nv_bfloat16 lb = __float2bfloat16(x - hf);
    l = (unsigned int)*reinterpret_cast<unsigned short*>(&lb);
}

static __device__ __forceinline__ void mma_bf16(
    float& c0, float& c1, float& c2, float& c3,
    unsigned a0, unsigned a1, unsigned a2, unsigned a3,
    unsigned b0, unsigned b1)
{
    asm volatile(
        "mma.sync.aligned.m16n8k16.row.col.f32.bf16.bf16.f32 "
        "{%0,%1,%2,%3}, {%4,%5,%6,%7}, {%8,%9}, {%0,%1,%2,%3};\n"
        : "+f"(c0), "+f"(c1), "+f"(c2), "+f"(c3)
        : "r"(a0), "r"(a1), "r"(a2), "r"(a3), "r"(b0), "r"(b1));
}

static __device__ __forceinline__ void ldsm_x4(
    unsigned& r0, unsigned& r1, unsigned& r2, unsigned& r3, unsigned addr)
{
    asm volatile("ldmatrix.sync.aligned.m8n8.x4.shared.b16 {%0,%1,%2,%3}, [%4];\n"
                 : "=r"(r0), "=r"(r1), "=r"(r2), "=r"(r3) : "r"(addr));
}
static __device__ __forceinline__ void ldsm_x4t(
    unsigned& r0, unsigned& r1, unsigned& r2, unsigned& r3, unsigned addr)
{
    asm volatile("ldmatrix.sync.aligned.m8n8.x4.trans.shared.b16 {%0,%1,%2,%3}, [%4];\n"
                 : "=r"(r0), "=r"(r1), "=r"(r2), "=r"(r3) : "r"(addr));
}

static __device__ __forceinline__ unsigned bf2u(__nv_bfloat162 v) {
    return *reinterpret_cast<unsigned*>(&v);
}

// Split a float4 into hi/lo bf16 pairs (2 u32 each)
static __device__ __forceinline__ void split4(float4 f, uint2& hi, uint2& lo) {
    __nv_bfloat162 h0 = __floats2bfloat162_rn(f.x, f.y);
    __nv_bfloat162 h1 = __floats2bfloat162_rn(f.z, f.w);
    float hx = __low2float(h0), hy = __high2float(h0);
    float hz = __low2float(h1), hw = __high2float(h1);
    __nv_bfloat162 l0 = __floats2bfloat162_rn(f.x - hx, f.y - hy);
    __nv_bfloat162 l1 = __floats2bfloat162_rn(f.z - hz, f.w - hw);
    hi.x = bf2u(h0); hi.y = bf2u(h1);
    lo.x = bf2u(l0); lo.y = bf2u(l1);
}

// ---------------------------------------------------------------------------
// Tensor-core GEMM with bf16 triple-K decomposition (unchanged from round 2).
// ---------------------------------------------------------------------------
static __device__ __forceinline__ void pack3_A(unsigned int* p, float x0, float x1) {
    unsigned int h0, l0, h1, l1; float f;
    bf_split(x0, h0, l0, f);
    bf_split(x1, h1, l1, f);
    p[0] = h0 | (l0 << 16);
    p[1] = h0 | (h1 << 16);
    p[2] = l1 | (h1 << 16);
}
static __device__ __forceinline__ void pack3_B(unsigned int* p, float x0, float x1) {
    unsigned int h0, l0, h1, l1; float f;
    bf_split(x0, h0, l0, f);
    bf_split(x1, h1, l1, f);
    p[0] = h0 | (h0 << 16);
    p[1] = l0 | (h1 << 16);
    p[2] = h1 | (l1 << 16);
}

#define WSTRIDE 28

__global__ __launch_bounds__(256) void gemm_tc_bias_kernel(
    const float* __restrict__ A, const float* __restrict__ B,
    const float* __restrict__ bias, float* __restrict__ C,
    int M, int N, int K)
{
    __shared__ unsigned int As32[128 * WSTRIDE];
    __shared__ unsigned int Bs32[128 * WSTRIDE];

    const int t    = threadIdx.x;
    const int bm   = blockIdx.y;
    const int bn   = blockIdx.x;
    const int wid  = t >> 5;
    const int lane = t & 31;
    const int warp_m = wid >> 1;
    const int warp_n = wid & 1;
    const int g = lane >> 2;
    const int q = lane & 3;

    const int aRow = t >> 2;
    const int bN0  = t & 31;

    const float* Abase = A + (size_t)(bm * 128 + aRow) * K + (t & 3) * 4;
    const float* Bbase = B + (size_t)(2 * (t >> 5)) * N + bn * 128 + bN0;

    float c[2][8][4];
    #pragma unroll
    for (int mf = 0; mf < 2; mf++)
        #pragma unroll
        for (int nf = 0; nf < 8; nf++)
            #pragma unroll
            for (int i = 0; i < 4; i++) c[mf][nf][i] = 0.f;

    const int nK = K / 16;

    float4 pa0 = *(const float4*)(Abase);
    float4 pa1 = *(const float4*)(Abase + (size_t)64 * K);
    float  pb[8];
    #pragma unroll
    for (int j = 0; j < 4; j++) {
        pb[2 * j + 0] = Bbase[(size_t)0 * N + 32 * j];
        pb[2 * j + 1] = Bbase[(size_t)1 * N + 32 * j];
    }

    for (int kt = 0; kt < nK; kt++) {
        __syncthreads();
        pack3_A(&As32[aRow * WSTRIDE + 6 * (t & 3) + 0], pa0.x, pa0.y);
        pack3_A(&As32[aRow * WSTRIDE + 6 * (t & 3) + 3], pa0.z, pa0.w);
        pack3_A(&As32[(aRow + 64) * WSTRIDE + 6 * (t & 3) + 0], pa1.x, pa1.y);
        pack3_A(&As32[(aRow + 64) * WSTRIDE + 6 * (t & 3) + 3], pa1.z, pa1.w);
        #pragma unroll
        for (int j = 0; j < 4; j++)
            pack3_B(&Bs32[(bN0 + 32 * j) * WSTRIDE + 3 * (t >> 5)],
                    pb[2 * j + 0], pb[2 * j + 1]);
        __syncthreads();

        if (kt + 1 < nK) {
            const float* An = Abase + (kt + 1) * 16;
            pa0 = *(const float4*)(An);
            pa1 = *(const float4*)(An + (size_t)64 * K);
            const float* Bn = Bbase + (size_t)(kt + 1) * 16 * N;
            #pragma unroll
            for (int j = 0; j < 4; j++) {
                pb[2 * j + 0] = Bn[(size_t)0 * N + 32 * j];
                pb[2 * j + 1] = Bn[(size_t)1 * N + 32 * j];
            }
        }

        #pragma unroll
        for (int s = 0; s < 3; s++) {
            unsigned int af[2][4];
            #pragma unroll
            for (int mf = 0; mf < 2; mf++) {
                const int mrow = warp_m * 32 + mf * 16 + g;
                const int idx = mrow * WSTRIDE + 8 * s + q;
                af[mf][0] = As32[idx];
                af[mf][1] = As32[idx + 8 * WSTRIDE];
                af[mf][2] = As32[idx + 4];
                af[mf][3] = As32[idx + 8 * WSTRIDE + 4];
            }
            #pragma unroll
            for (int nf = 0; nf < 8; nf++) {
                const int nrow = warp_n * 64 + nf * 8 + g;
                const int idx = nrow * WSTRIDE + 8 * s + q;
                unsigned int b0 = Bs32[idx];
                unsigned int b1 = Bs32[idx + 4];
                mma_bf16(c[0][nf][0], c[0][nf][1], c[0][nf][2], c[0][nf][3],
                         af[0][0], af[0][1], af[0][2], af[0][3], b0, b1);
                mma_bf16(c[1][nf][0], c[1][nf][1], c[1][nf][2], c[1][nf][3],
                         af[1][0], af[1][1], af[1][2], af[1][3], b0, b1);
            }
        }
    }

    const int crow0 = bm * 128 + warp_m * 32 + g;
    const int ccol0 = bn * 128 + warp_n * 64 + 2 * q;
    #pragma unroll
    for (int nf = 0; nf < 8; nf++) {
        const int col = ccol0 + nf * 8;
        const float bx = bias[col];
        const float by = bias[col + 1];
        #pragma unroll
        for (int mf = 0; mf < 2; mf++) {
            const int row = crow0 + mf * 16;
            float2 w0 = make_float2(c[mf][nf][0] + bx, c[mf][nf][1] + by);
            float2 w1 = make_float2(c[mf][nf][2] + bx, c[mf][nf][3] + by);
            *(float2*)(C + (size_t)row * N + col) = w0;
            *(float2*)(C + (size_t)(row + 8) * N + col) = w1;
        }
    }
}

// ---------------------------------------------------------------------------
// Tensor-core flash attention (causal), triple-bf16 split for QK^T and PV.
// Grid: (16, NHEADS, BATCH), 256 threads (8 warps x 16 q-rows = 128 q rows).
// kv tiles of 64. Dynamic smem: Q/K/V hi+lo bf16 planes, row stride 136 halves.
// ---------------------------------------------------------------------------
#define ATT_C 0.12751666769323707f  // (1/sqrt(128)) * log2(e)
#define RSTR  136                   // halves per smem row (128 + 8 pad)
// half offsets within dynamic smem
#define QH_OFF 0
#define QL_OFF 17408
#define KH_OFF 34816
#define KL_OFF 43520
#define VH_OFF 52224
#define VL_OFF 60928
#define ATT_SMEM_BYTES (69632 * 2)

__global__ __launch_bounds__(256) void flash_attn_tc_kernel(
    const float* __restrict__ qkv, float* __restrict__ out)
{
    extern __shared__ unsigned smu[];   // u32 view of bf16 smem
    const unsigned sbase = (unsigned)__cvta_generic_to_shared(smu);

    const int qblk = blockIdx.x;
    const int h    = blockIdx.y;
    const int b    = blockIdx.z;
    const int tid  = threadIdx.x;
    const int lane = tid & 31;
    const int w    = tid >> 5;
    const int g    = lane >> 2;
    const int q    = lane & 3;

    // ---- Load Q tile (128 rows x 128 d), split hi/lo, into smem
    {
        const int r  = tid >> 1;
        const int c0 = (tid & 1) * 64;
        const float* qb = qkv + (size_t)(b * SEQ + qblk * 128 + r) * DM3 + h * DHEAD + c0;
        #pragma unroll
        for (int i = 0; i < 16; i++) {
            float4 f = *(const float4*)(qb + 4 * i);
            uint2 hi, lo;
            split4(f, hi, lo);
            const int widx = r * (RSTR / 2) + c0 / 2 + 2 * i;
            *(uint2*)(smu + QH_OFF / 2 + widx) = hi;
            *(uint2*)(smu + QL_OFF / 2 + widx) = lo;
        }
    }
    __syncthreads();

    // ---- Cache Q fragments in registers (per warp: rows 16w..16w+15)
    unsigned qh[8][4], ql[8][4];
    {
        const int row = 16 * w + (lane & 15);
        const int cb  = 8 * (lane >> 4);
        #pragma unroll
        for (int ds = 0; ds < 8; ds++) {
            unsigned a = sbase + 2 * (QH_OFF + row * RSTR + 16 * ds + cb);
            ldsm_x4(qh[ds][0], qh[ds][1], qh[ds][2], qh[ds][3], a);
            ldsm_x4(ql[ds][0], ql[ds][1], ql[ds][2], ql[ds][3],
                    a + 2 * (QL_OFF - QH_OFF));
        }
    }

    float o[16][4];
    #pragma unroll
    for (int nf = 0; nf < 16; nf++)
        #pragma unroll
        for (int i = 0; i < 4; i++) o[nf][i] = 0.f;
    float m0 = -1e30f, m1 = -1e30f, l0 = 0.f, l1 = 0.f;

    const int ntiles = 2 * qblk + 2;
    const int warp_row_max = qblk * 128 + 16 * w + 15;

    for (int kt = 0; kt < ntiles; kt++) {
        __syncthreads();
        // ---- Load K,V tile (64 rows x 128 d), split hi/lo
        {
            const int r  = tid >> 2;
            const int c0 = (tid & 3) * 32;
            const float* kb = qkv + (size_t)(b * SEQ + kt * 64 + r) * DM3
                              + h * DHEAD + DMODEL + c0;
            const float* vb = kb + DMODEL;
            #pragma unroll
            for (int i = 0; i < 8; i++) {
                float4 fk = *(const float4*)(kb + 4 * i);
                float4 fv = *(const float4*)(vb + 4 * i);
                uint2 hi, lo;
                const int widx = r * (RSTR / 2) + c0 / 2 + 2 * i;
                split4(fk, hi, lo);
                *(uint2*)(smu + KH_OFF / 2 + widx) = hi;
                *(uint2*)(smu + KL_OFF / 2 + widx) = lo;
                split4(fv, hi, lo);
                *(uint2*)(smu + VH_OFF / 2 + widx) = hi;
                *(uint2*)(smu + VL_OFF / 2 + widx) = lo;
            }
        }
        __syncthreads();

        if (kt * 64 > warp_row_max) continue;   // fully masked for this warp

        // ---- Scores S = Q K^T (triple-split bf16 mma)
        float s[8][4];
        #pragma unroll
        for (int nf = 0; nf < 8; nf++)
            #pragma unroll
            for (int i = 0; i < 4; i++) s[nf][i] = 0.f;

        {
            const int krow   = (lane & 7) + 8 * (lane >> 4);
            const int kchunk = 8 * ((lane >> 3) & 1);
            #pragma unroll
            for (int ds = 0; ds < 8; ds++) {
                #pragma unroll
                for (int nfp = 0; nfp < 4; nfp++) {
                    unsigned a = sbase + 2 * (KH_OFF + (16 * nfp + krow) * RSTR
                                              + 16 * ds + kchunk);
                    unsigned bh0, bh1, bh2, bh3, bl0, bl1, bl2, bl3;
                    ldsm_x4(bh0, bh1, bh2, bh3, a);
                    ldsm_x4(bl0, bl1, bl2, bl3, a + 2 * (KL_OFF - KH_OFF));
                    float* s0 = s[2 * nfp];
                    float* s1 = s[2 * nfp + 1];
                    mma_bf16(s0[0], s0[1], s0[2], s0[3],
                             qh[ds][0], qh[ds][1], qh[ds][2], qh[ds][3], bh0, bh1);
                    mma_bf16(s0[0], s0[1], s0[2], s0[3],
                             ql[ds][0], ql[ds][1], ql[ds][2], ql[ds][3], bh0, bh1);
                    mma_bf16(s0[0], s0[1], s0[2], s0[3],
                             qh[ds][0], qh[ds][1], qh[ds][2], qh[ds][3], bl0, bl1);
                    mma_bf16(s1[0], s1[1], s1[2], s1[3],
                             qh[ds][0], qh[ds][1], qh[ds][2], qh[ds][3], bh2, bh3);
                    mma_bf16(s1[0], s1[1], s1[2], s1[3],
                             ql[ds][0], ql[ds][1], ql[ds][2], ql[ds][3], bh2, bh3);
                    mma_bf16(s1[0], s1[1], s1[2], s1[3],
                             qh[ds][0], qh[ds][1], qh[ds][2], qh[ds][3], bl2, bl3);
                }
            }
        }

        // ---- Causal mask (only the two diagonal-crossing tiles)
        if (kt >= 2 * qblk) {
            const int row0 = qblk * 128 + 16 * w + g;
            #pragma unroll
            for (int nf = 0; nf < 8; nf++) {
                const int col = kt * 64 + 8 * nf + 2 * q;
                if (col     > row0)     s[nf][0] = -CUDART_INF_F;
                if (col + 1 > row0)     s[nf][1] = -CUDART_INF_F;
                if (col     > row0 + 8) s[nf][2] = -CUDART_INF_F;
                if (col + 1 > row0 + 8) s[nf][3] = -CUDART_INF_F;
            }
        }

        // ---- Online softmax in fragment layout
        float tm0 = -CUDART_INF_F, tm1 = -CUDART_INF_F;
        #pragma unroll
        for (int nf = 0; nf < 8; nf++) {
            tm0 = fmaxf(tm0, fmaxf(s[nf][0], s[nf][1]));
            tm1 = fmaxf(tm1, fmaxf(s[nf][2], s[nf][3]));
        }
        tm0 = fmaxf(tm0, __shfl_xor_sync(0xffffffffu, tm0, 1));
        tm0 = fmaxf(tm0, __shfl_xor_sync(0xffffffffu, tm0, 2));
        tm1 = fmaxf(tm1, __shfl_xor_sync(0xffffffffu, tm1, 1));
        tm1 = fmaxf(tm1, __shfl_xor_sync(0xffffffffu, tm1, 2));

        const float m0n = fmaxf(m0, tm0);
        const float m1n = fmaxf(m1, tm1);
        const float cr0 = exp2f((m0 - m0n) * ATT_C);
        const float cr1 = exp2f((m1 - m1n) * ATT_C);
        m0 = m0n; m1 = m1n;
        l0 *= cr0; l1 *= cr1;
        #pragma unroll
        for (int nf = 0; nf < 16; nf++) {
            o[nf][0] *= cr0; o[nf][1] *= cr0;
            o[nf][2] *= cr1; o[nf][3] *= cr1;
        }

        unsigned ph[8][2], pl[8][2];
        #pragma unroll
        for (int nf = 0; nf < 8; nf++) {
            float p0 = exp2f((s[nf][0] - m0) * ATT_C);
            float p1 = exp2f((s[nf][1] - m0) * ATT_C);
            float p2 = exp2f((s[nf][2] - m1) * ATT_C);
            float p3 = exp2f((s[nf][3] - m1) * ATT_C);
            l0 += p0 + p1;
            l1 += p2 + p3;
            __nv_bfloat162 h01 = __floats2bfloat162_rn(p0, p1);
            __nv_bfloat162 h23 = __floats2bfloat162_rn(p2, p3);
            __nv_bfloat162 e01 = __floats2bfloat162_rn(p0 - __low2float(h01),
                                                       p1 - __high2float(h01));
            __nv_bfloat162 e23 = __floats2bfloat162_rn(p2 - __low2float(h23),
                                                       p3 - __high2float(h23));
            ph[nf][0] = bf2u(h01); ph[nf][1] = bf2u(h23);
            pl[nf][0] = bf2u(e01); pl[nf][1] = bf2u(e23);
        }

        // ---- O += P V (triple-split)
        {
            const int vrow   = (lane & 15);
            const int vchunk = 8 * (lane >> 4);
            #pragma unroll
            for (int j = 0; j < 4; j++) {
                const unsigned ah0 = ph[2 * j][0],     ah1 = ph[2 * j][1];
                const unsigned ah2 = ph[2 * j + 1][0], ah3 = ph[2 * j + 1][1];
                const unsigned al0 = pl[2 * j][0],     al1 = pl[2 * j][1];
                const unsigned al2 = pl[2 * j + 1][0], al3 = pl[2 * j + 1][1];
                #pragma unroll
                for (int nfp = 0; nfp < 8; nfp++) {
                    unsigned a = sbase + 2 * (VH_OFF + (16 * j + vrow) * RSTR
                                              + 16 * nfp + vchunk);
                    unsigned vh0, vh1, vh2, vh3, vl0, vl1, vl2, vl3;
                    ldsm_x4t(vh0, vh1, vh2, vh3, a);
                    ldsm_x4t(vl0, vl1, vl2, vl3, a + 2 * (VL_OFF - VH_OFF));
                    float* o0 = o[2 * nfp];
                    float* o1 = o[2 * nfp + 1];
                    mma_bf16(o0[0], o0[1], o0[2], o0[3], ah0, ah1, ah2, ah3, vh0, vh1);
                    mma_bf16(o0[0], o0[1], o0[2], o0[3], al0, al1, al2, al3, vh0, vh1);
                    mma_bf16(o0[0], o0[1], o0[2], o0[3], ah0, ah1, ah2, ah3, vl0, vl1);
                    mma_bf16(o1[0], o1[1], o1[2], o1[3], ah0, ah1, ah2, ah3, vh2, vh3);
                    mma_bf16(o1[0], o1[1], o1[2], o1[3], al0, al1, al2, al3, vh2, vh3);
                    mma_bf16(o1[0], o1[1], o1[2], o1[3], ah0, ah1, ah2, ah3, vl2, vl3);
                }
            }
        }
    }

    // ---- Epilogue: normalize and store
    l0 += __shfl_xor_sync(0xffffffffu, l0, 1);
    l0 += __shfl_xor_sync(0xffffffffu, l0, 2);
    l1 += __shfl_xor_sync(0xffffffffu, l1, 1);
    l1 += __shfl_xor_sync(0xffffffffu, l1, 2);
    const float inv0 = 1.f / l0;
    const float inv1 = 1.f / l1;

    const int row0 = b * SEQ + qblk * 128 + 16 * w + g;
    float* ob = out + (size_t)row0 * DMODEL + h * DHEAD;
    #pragma unroll
    for (int nf = 0; nf < 16; nf++) {
        const int col = 8 * nf + 2 * q;
        *(float2*)(ob + col) =
            make_float2(o[nf][0] * inv0, o[nf][1] * inv0);
        *(float2*)(ob + 8 * DMODEL + col) =
            make_float2(o[nf][2] * inv1, o[nf][3] * inv1);
    }
}

// ---------------------------------------------------------------------------
// kernel_launch
// ---------------------------------------------------------------------------
extern "C" void kernel_launch(void* const* d_in, const int* in_sizes, int n_in,
                              void* d_out, int out_size)
{
    const float* x     = (const float*)d_in[0];
    const float* W_qkv = (const float*)d_in[1];
    const float* b_qkv = (const float*)d_in[2];
    const float* W_out = (const float*)d_in[3];
    const float* b_out = (const float*)d_in[4];
    float* out = (float*)d_out;

    float* qkv;
    float* attn;
    cudaGetSymbolAddress((void**)&qkv, g_qkv);
    cudaGetSymbolAddress((void**)&attn, g_attn);

    cudaFuncSetAttribute(flash_attn_tc_kernel,
                         cudaFuncAttributeMaxDynamicSharedMemorySize,
                         ATT_SMEM_BYTES);

    gemm_tc_bias_kernel<<<dim3(DM3 / 128, MTOT / 128), 256>>>(
        x, W_qkv, b_qkv, qkv, MTOT, DM3, DMODEL);

    flash_attn_tc_kernel<<<dim3(16, NHEADS, BATCH), 256, ATT_SMEM_BYTES>>>(
        qkv, attn);

    gemm_tc_bias_kernel<<<dim3(DMODEL / 128, MTOT / 128), 256>>>(
        attn, W_out, b_out, out, MTOT, DMODEL, DMODEL);
}

// round 5
// speedup vs baseline: 3.1778x; 1.3019x over previous
#include <cuda_runtime.h>
#include <cuda_bf16.h>
#include <math_constants.h>

#define BATCH   2
#define SEQ     2048
#define NHEADS  16
#define DHEAD   128
#define DMODEL  2048
#define DM3     6144
#define MTOT    4096

// Scratch (device globals)
__device__ float         g_qkv[(size_t)MTOT * DM3];        // fp32 qkv for attention
__device__ __nv_bfloat16 g_xh[(size_t)MTOT * DMODEL];
__device__ __nv_bfloat16 g_xl[(size_t)MTOT * DMODEL];
__device__ __nv_bfloat16 g_wqkvth[(size_t)DM3 * DMODEL];   // [N=6144][K=2048]
__device__ __nv_bfloat16 g_wqkvtl[(size_t)DM3 * DMODEL];
__device__ __nv_bfloat16 g_woutth[(size_t)DMODEL * DMODEL];
__device__ __nv_bfloat16 g_wouttl[(size_t)DMODEL * DMODEL];
__device__ __nv_bfloat16 g_attnh[(size_t)MTOT * DMODEL];
__device__ __nv_bfloat16 g_attnl[(size_t)MTOT * DMODEL];

// ---------------------------------------------------------------------------
// Helpers
// ---------------------------------------------------------------------------
static __device__ __forceinline__ void mma_bf16(
    float& c0, float& c1, float& c2, float& c3,
    unsigned a0, unsigned a1, unsigned a2, unsigned a3,
    unsigned b0, unsigned b1)
{
    asm volatile(
        "mma.sync.aligned.m16n8k16.row.col.f32.bf16.bf16.f32 "
        "{%0,%1,%2,%3}, {%4,%5,%6,%7}, {%8,%9}, {%0,%1,%2,%3};\n"
        : "+f"(c0), "+f"(c1), "+f"(c2), "+f"(c3)
        : "r"(a0), "r"(a1), "r"(a2), "r"(a3), "r"(b0), "r"(b1));
}
static __device__ __forceinline__ void ldsm_x4(
    unsigned& r0, unsigned& r1, unsigned& r2, unsigned& r3, unsigned addr)
{
    asm volatile("ldmatrix.sync.aligned.m8n8.x4.shared.b16 {%0,%1,%2,%3}, [%4];\n"
                 : "=r"(r0), "=r"(r1), "=r"(r2), "=r"(r3) : "r"(addr));
}
static __device__ __forceinline__ void ldsm_x4t(
    unsigned& r0, unsigned& r1, unsigned& r2, unsigned& r3, unsigned addr)
{
    asm volatile("ldmatrix.sync.aligned.m8n8.x4.trans.shared.b16 {%0,%1,%2,%3}, [%4];\n"
                 : "=r"(r0), "=r"(r1), "=r"(r2), "=r"(r3) : "r"(addr));
}
static __device__ __forceinline__ unsigned bf2u(__nv_bfloat162 v) {
    return *reinterpret_cast<unsigned*>(&v);
}
static __device__ __forceinline__ void split4(float4 f, uint2& hi, uint2& lo) {
    __nv_bfloat162 h0 = __floats2bfloat162_rn(f.x, f.y);
    __nv_bfloat162 h1 = __floats2bfloat162_rn(f.z, f.w);
    float hx = __low2float(h0), hy = __high2float(h0);
    float hz = __low2float(h1), hw = __high2float(h1);
    __nv_bfloat162 l0 = __floats2bfloat162_rn(f.x - hx, f.y - hy);
    __nv_bfloat162 l1 = __floats2bfloat162_rn(f.z - hz, f.w - hw);
    hi.x = bf2u(h0); hi.y = bf2u(h1);
    lo.x = bf2u(l0); lo.y = bf2u(l1);
}
static __device__ __forceinline__ void cpa16(unsigned saddr, const void* g) {
    asm volatile("cp.async.cg.shared.global [%0], [%1], 16;\n"
                 :: "r"(saddr), "l"(g));
}

// ---------------------------------------------------------------------------
// Prep kernels: fp32 -> bf16 hi/lo planes
// ---------------------------------------------------------------------------
__global__ __launch_bounds__(256) void split_rm_kernel(
    const float4* __restrict__ src, uint2* __restrict__ h, uint2* __restrict__ l,
    int n4)
{
    int i = blockIdx.x * 256 + threadIdx.x;
    if (i < n4) {
        uint2 hi, lo;
        split4(src[i], hi, lo);
        h[i] = hi; l[i] = lo;
    }
}

// W [K][N] fp32 -> Wt hi/lo [N][K] bf16
__global__ __launch_bounds__(256) void split_tr_kernel(
    const float* __restrict__ W,
    __nv_bfloat16* __restrict__ th, __nv_bfloat16* __restrict__ tl,
    int K, int N)
{
    __shared__ float tile[32][33];
    const int n0 = blockIdx.x * 32, k0 = blockIdx.y * 32;
    const int tx = threadIdx.x & 31, ty = threadIdx.x >> 5;  // 32 x 8
    #pragma unroll
    for (int i = 0; i < 32; i += 8)
        tile[ty + i][tx] = W[(size_t)(k0 + ty + i) * N + (n0 + tx)];
    __syncthreads();
    #pragma unroll
    for (int i = 0; i < 32; i += 8) {
        float v = tile[tx][ty + i];
        __nv_bfloat16 hb = __float2bfloat16(v);
        __nv_bfloat16 lb = __float2bfloat16(v - __bfloat162float(hb));
        size_t o = (size_t)(n0 + ty + i) * K + (k0 + tx);
        th[o] = hb; tl[o] = lb;
    }
}

// ---------------------------------------------------------------------------
// Plane GEMM: C[M,N] = (Ah+Al)[M,K] @ (Bh+Bl)^T[N,K] + bias
// (triple product: AhBh + AlBh + AhBl)
// Block 128x128, ktile 32, cp.async double-buffered, ldmatrix fragments.
// 256 threads = 8 warps (4m x 2n), warp tile 32m x 64n.
// ---------------------------------------------------------------------------
#define GST 40                       // halves per smem row (32 + 8 pad)
#define PLN (128 * GST)              // plane size in halves (5120)
#define BUFH (4 * PLN)               // buffer stride in halves (20480)
#define GEMM_SMEM_BYTES (2 * BUFH * 2)

__global__ __launch_bounds__(256) void gemm_planes_bias_kernel(
    const __nv_bfloat16* __restrict__ Ah, const __nv_bfloat16* __restrict__ Al,
    const __nv_bfloat16* __restrict__ Bh, const __nv_bfloat16* __restrict__ Bl,
    const float* __restrict__ bias, float* __restrict__ C,
    int M, int N, int K)
{
    extern __shared__ __nv_bfloat16 sm[];
    const unsigned sb = (unsigned)__cvta_generic_to_shared(sm);

    const int t = threadIdx.x, lane = t & 31, wid = t >> 5;
    const int bm = blockIdx.y, bn = blockIdx.x;
    const int warp_m = wid >> 1, warp_n = wid & 1;

    const int lr = t >> 1;
    const int ls = (t & 1) * 16;
    const __nv_bfloat16* Ahg = Ah + (size_t)(bm * 128 + lr) * K + ls;
    const __nv_bfloat16* Alg = Al + (size_t)(bm * 128 + lr) * K + ls;
    const __nv_bfloat16* Bhg = Bh + (size_t)(bn * 128 + lr) * K + ls;
    const __nv_bfloat16* Blg = Bl + (size_t)(bn * 128 + lr) * K + ls;
    const unsigned sAd = sb + 2 * (lr * GST + ls);

    float c[2][8][4];
    #pragma unroll
    for (int mf = 0; mf < 2; mf++)
        #pragma unroll
        for (int nf = 0; nf < 8; nf++)
            #pragma unroll
            for (int i = 0; i < 4; i++) c[mf][nf][i] = 0.f;

    const int nK = K / 32;

    // Prologue: tile 0 into buf 0
    {
        unsigned d = sAd;
        cpa16(d,                 Ahg);
        cpa16(d + 16,            Ahg + 8);
        cpa16(d + 2 * PLN,       Alg);
        cpa16(d + 2 * PLN + 16,  Alg + 8);
        cpa16(d + 4 * PLN,       Bhg);
        cpa16(d + 4 * PLN + 16,  Bhg + 8);
        cpa16(d + 6 * PLN,       Blg);
        cpa16(d + 6 * PLN + 16,  Blg + 8);
        asm volatile("cp.async.commit_group;\n" ::: "memory");
    }

    int buf = 0;
    for (int kt = 0; kt < nK; kt++) {
        asm volatile("cp.async.wait_group 0;\n" ::: "memory");
        __syncthreads();

        if (kt + 1 < nK) {
            const int go = (kt + 1) * 32;
            unsigned d = sAd + 2 * (buf ^ 1) * BUFH;
            cpa16(d,                 Ahg + go);
            cpa16(d + 16,            Ahg + go + 8);
            cpa16(d + 2 * PLN,       Alg + go);
            cpa16(d + 2 * PLN + 16,  Alg + go + 8);
            cpa16(d + 4 * PLN,       Bhg + go);
            cpa16(d + 4 * PLN + 16,  Bhg + go + 8);
            cpa16(d + 6 * PLN,       Blg + go);
            cpa16(d + 6 * PLN + 16,  Blg + go + 8);
            asm volatile("cp.async.commit_group;\n" ::: "memory");
        }

        const unsigned base = sb + 2 * buf * BUFH;
        #pragma unroll
        for (int s = 0; s < 2; s++) {
            unsigned ah[2][4], al[2][4];
            #pragma unroll
            for (int mf = 0; mf < 2; mf++) {
                const int row = warp_m * 32 + mf * 16 + (lane & 15);
                const unsigned a = base + 2 * (row * GST + 16 * s + 8 * (lane >> 4));
                ldsm_x4(ah[mf][0], ah[mf][1], ah[mf][2], ah[mf][3], a);
                ldsm_x4(al[mf][0], al[mf][1], al[mf][2], al[mf][3], a + 2 * PLN);
            }
            #pragma unroll
            for (int nfp = 0; nfp < 4; nfp++) {
                const int nrow = warp_n * 64 + nfp * 16 + (lane & 7) + 8 * (lane >> 4);
                const unsigned a = base + 2 * (2 * PLN + nrow * GST
                                               + 16 * s + 8 * ((lane >> 3) & 1));
                unsigned bh0, bh1, bh2, bh3, bl0, bl1, bl2, bl3;
                ldsm_x4(bh0, bh1, bh2, bh3, a);
                ldsm_x4(bl0, bl1, bl2, bl3, a + 2 * PLN);
                #pragma unroll
                for (int mf = 0; mf < 2; mf++) {
                    float* c0 = c[mf][2 * nfp];
                    float* c1 = c[mf][2 * nfp + 1];
                    mma_bf16(c0[0], c0[1], c0[2], c0[3],
                             ah[mf][0], ah[mf][1], ah[mf][2], ah[mf][3], bh0, bh1);
                    mma_bf16(c0[0], c0[1], c0[2], c0[3],
                             al[mf][0], al[mf][1], al[mf][2], al[mf][3], bh0, bh1);
                    mma_bf16(c0[0], c0[1], c0[2], c0[3],
                             ah[mf][0], ah[mf][1], ah[mf][2], ah[mf][3], bl0, bl1);
                    mma_bf16(c1[0], c1[1], c1[2], c1[3],
                             ah[mf][0], ah[mf][1], ah[mf][2], ah[mf][3], bh2, bh3);
                    mma_bf16(c1[0], c1[1], c1[2], c1[3],
                             al[mf][0], al[mf][1], al[mf][2], al[mf][3], bh2, bh3);
                    mma_bf16(c1[0], c1[1], c1[2], c1[3],
                             ah[mf][0], ah[mf][1], ah[mf][2], ah[mf][3], bl2, bl3);
                }
            }
        }
        buf ^= 1;
    }

    // Epilogue: bias + store
    const int g = lane >> 2, q = lane & 3;
    const int crow0 = bm * 128 + warp_m * 32 + g;
    const int ccol0 = bn * 128 + warp_n * 64 + 2 * q;
    #pragma unroll
    for (int nf = 0; nf < 8; nf++) {
        const int col = ccol0 + nf * 8;
        const float bx = bias[col];
        const float by = bias[col + 1];
        #pragma unroll
        for (int mf = 0; mf < 2; mf++) {
            const int row = crow0 + mf * 16;
            *(float2*)(C + (size_t)row * N + col) =
                make_float2(c[mf][nf][0] + bx, c[mf][nf][1] + by);
            *(float2*)(C + (size_t)(row + 8) * N + col) =
                make_float2(c[mf][nf][2] + bx, c[mf][nf][3] + by);
        }
    }
}

// ---------------------------------------------------------------------------
// Tensor-core flash attention (causal), triple-bf16; writes bf16 hi/lo planes.
// ---------------------------------------------------------------------------
#define ATT_C 0.12751666769323707f  // (1/sqrt(128)) * log2(e)
#define RSTR  136
#define QH_OFF 0
#define QL_OFF 17408
#define KH_OFF 34816
#define KL_OFF 43520
#define VH_OFF 52224
#define VL_OFF 60928
#define ATT_SMEM_BYTES (69632 * 2)

__global__ __launch_bounds__(256) void flash_attn_tc_kernel(
    const float* __restrict__ qkv,
    __nv_bfloat16* __restrict__ outh, __nv_bfloat16* __restrict__ outl)
{
    extern __shared__ unsigned smu[];
    const unsigned sbase = (unsigned)__cvta_generic_to_shared(smu);

    const int qblk = blockIdx.x;
    const int h    = blockIdx.y;
    const int b    = blockIdx.z;
    const int tid  = threadIdx.x;
    const int lane = tid & 31;
    const int w    = tid >> 5;
    const int g    = lane >> 2;
    const int q    = lane & 3;

    {
        const int r  = tid >> 1;
        const int c0 = (tid & 1) * 64;
        const float* qb = qkv + (size_t)(b * SEQ + qblk * 128 + r) * DM3 + h * DHEAD + c0;
        #pragma unroll
        for (int i = 0; i < 16; i++) {
            float4 f = *(const float4*)(qb + 4 * i);
            uint2 hi, lo;
            split4(f, hi, lo);
            const int widx = r * (RSTR / 2) + c0 / 2 + 2 * i;
            *(uint2*)(smu + QH_OFF / 2 + widx) = hi;
            *(uint2*)(smu + QL_OFF / 2 + widx) = lo;
        }
    }
    __syncthreads();

    unsigned qh[8][4], ql[8][4];
    {
        const int row = 16 * w + (lane & 15);
        const int cb  = 8 * (lane >> 4);
        #pragma unroll
        for (int ds = 0; ds < 8; ds++) {
            unsigned a = sbase + 2 * (QH_OFF + row * RSTR + 16 * ds + cb);
            ldsm_x4(qh[ds][0], qh[ds][1], qh[ds][2], qh[ds][3], a);
            ldsm_x4(ql[ds][0], ql[ds][1], ql[ds][2], ql[ds][3],
                    a + 2 * (QL_OFF - QH_OFF));
        }
    }

    float o[16][4];
    #pragma unroll
    for (int nf = 0; nf < 16; nf++)
        #pragma unroll
        for (int i = 0; i < 4; i++) o[nf][i] = 0.f;
    float m0 = -1e30f, m1 = -1e30f, l0 = 0.f, l1 = 0.f;

    const int ntiles = 2 * qblk + 2;
    const int warp_row_max = qblk * 128 + 16 * w + 15;

    for (int kt = 0; kt < ntiles; kt++) {
        __syncthreads();
        {
            const int r  = tid >> 2;
            const int c0 = (tid & 3) * 32;
            const float* kb = qkv + (size_t)(b * SEQ + kt * 64 + r) * DM3
                              + h * DHEAD + DMODEL + c0;
            const float* vb = kb + DMODEL;
            #pragma unroll
            for (int i = 0; i < 8; i++) {
                float4 fk = *(const float4*)(kb + 4 * i);
                float4 fv = *(const float4*)(vb + 4 * i);
                uint2 hi, lo;
                const int widx = r * (RSTR / 2) + c0 / 2 + 2 * i;
                split4(fk, hi, lo);
                *(uint2*)(smu + KH_OFF / 2 + widx) = hi;
                *(uint2*)(smu + KL_OFF / 2 + widx) = lo;
                split4(fv, hi, lo);
                *(uint2*)(smu + VH_OFF / 2 + widx) = hi;
                *(uint2*)(smu + VL_OFF / 2 + widx) = lo;
            }
        }
        __syncthreads();

        if (kt * 64 > warp_row_max) continue;

        float s[8][4];
        #pragma unroll
        for (int nf = 0; nf < 8; nf++)
            #pragma unroll
            for (int i = 0; i < 4; i++) s[nf][i] = 0.f;

        {
            const int krow   = (lane & 7) + 8 * (lane >> 4);
            const int kchunk = 8 * ((lane >> 3) & 1);
            #pragma unroll
            for (int ds = 0; ds < 8; ds++) {
                #pragma unroll
                for (int nfp = 0; nfp < 4; nfp++) {
                    unsigned a = sbase + 2 * (KH_OFF + (16 * nfp + krow) * RSTR
                                              + 16 * ds + kchunk);
                    unsigned bh0, bh1, bh2, bh3, bl0, bl1, bl2, bl3;
                    ldsm_x4(bh0, bh1, bh2, bh3, a);
                    ldsm_x4(bl0, bl1, bl2, bl3, a + 2 * (KL_OFF - KH_OFF));
                    float* s0 = s[2 * nfp];
                    float* s1 = s[2 * nfp + 1];
                    mma_bf16(s0[0], s0[1], s0[2], s0[3],
                             qh[ds][0], qh[ds][1], qh[ds][2], qh[ds][3], bh0, bh1);
                    mma_bf16(s0[0], s0[1], s0[2], s0[3],
                             ql[ds][0], ql[ds][1], ql[ds][2], ql[ds][3], bh0, bh1);
                    mma_bf16(s0[0], s0[1], s0[2], s0[3],
                             qh[ds][0], qh[ds][1], qh[ds][2], qh[ds][3], bl0, bl1);
                    mma_bf16(s1[0], s1[1], s1[2], s1[3],
                             qh[ds][0], qh[ds][1], qh[ds][2], qh[ds][3], bh2, bh3);
                    mma_bf16(s1[0], s1[1], s1[2], s1[3],
                             ql[ds][0], ql[ds][1], ql[ds][2], ql[ds][3], bh2, bh3);
                    mma_bf16(s1[0], s1[1], s1[2], s1[3],
                             qh[ds][0], qh[ds][1], qh[ds][2], qh[ds][3], bl2, bl3);
                }
            }
        }

        if (kt >= 2 * qblk) {
            const int row0 = qblk * 128 + 16 * w + g;
            #pragma unroll
            for (int nf = 0; nf < 8; nf++) {
                const int col = kt * 64 + 8 * nf + 2 * q;
                if (col     > row0)     s[nf][0] = -CUDART_INF_F;
                if (col + 1 > row0)     s[nf][1] = -CUDART_INF_F;
                if (col     > row0 + 8) s[nf][2] = -CUDART_INF_F;
                if (col + 1 > row0 + 8) s[nf][3] = -CUDART_INF_F;
            }
        }

        float tm0 = -CUDART_INF_F, tm1 = -CUDART_INF_F;
        #pragma unroll
        for (int nf = 0; nf < 8; nf++) {
            tm0 = fmaxf(tm0, fmaxf(s[nf][0], s[nf][1]));
            tm1 = fmaxf(tm1, fmaxf(s[nf][2], s[nf][3]));
        }
        tm0 = fmaxf(tm0, __shfl_xor_sync(0xffffffffu, tm0, 1));
        tm0 = fmaxf(tm0, __shfl_xor_sync(0xffffffffu, tm0, 2));
        tm1 = fmaxf(tm1, __shfl_xor_sync(0xffffffffu, tm1, 1));
        tm1 = fmaxf(tm1, __shfl_xor_sync(0xffffffffu, tm1, 2));

        const float m0n = fmaxf(m0, tm0);
        const float m1n = fmaxf(m1, tm1);
        const float cr0 = exp2f((m0 - m0n) * ATT_C);
        const float cr1 = exp2f((m1 - m1n) * ATT_C);
        m0 = m0n; m1 = m1n;
        l0 *= cr0; l1 *= cr1;
        #pragma unroll
        for (int nf = 0; nf < 16; nf++) {
            o[nf][0] *= cr0; o[nf][1] *= cr0;
            o[nf][2] *= cr1; o[nf][3] *= cr1;
        }

        unsigned ph[8][2], pl[8][2];
        #pragma unroll
        for (int nf = 0; nf < 8; nf++) {
            float p0 = exp2f((s[nf][0] - m0) * ATT_C);
            float p1 = exp2f((s[nf][1] - m0) * ATT_C);
            float p2 = exp2f((s[nf][2] - m1) * ATT_C);
            float p3 = exp2f((s[nf][3] - m1) * ATT_C);
            l0 += p0 + p1;
            l1 += p2 + p3;
            __nv_bfloat162 h01 = __floats2bfloat162_rn(p0, p1);
            __nv_bfloat162 h23 = __floats2bfloat162_rn(p2, p3);
            __nv_bfloat162 e01 = __floats2bfloat162_rn(p0 - __low2float(h01),
                                                       p1 - __high2float(h01));
            __nv_bfloat162 e23 = __floats2bfloat162_rn(p2 - __low2float(h23),
                                                       p3 - __high2float(h23));
            ph[nf][0] = bf2u(h01); ph[nf][1] = bf2u(h23);
            pl[nf][0] = bf2u(e01); pl[nf][1] = bf2u(e23);
        }

        {
            const int vrow   = (lane & 15);
            const int vchunk = 8 * (lane >> 4);
            #pragma unroll
            for (int j = 0; j < 4; j++) {
                const unsigned ah0 = ph[2 * j][0],     ah1 = ph[2 * j][1];
                const unsigned ah2 = ph[2 * j + 1][0], ah3 = ph[2 * j + 1][1];
                const unsigned al0 = pl[2 * j][0],     al1 = pl[2 * j][1];
                const unsigned al2 = pl[2 * j + 1][0], al3 = pl[2 * j + 1][1];
                #pragma unroll
                for (int nfp = 0; nfp < 8; nfp++) {
                    unsigned a = sbase + 2 * (VH_OFF + (16 * j + vrow) * RSTR
                                              + 16 * nfp + vchunk);
                    unsigned vh0, vh1, vh2, vh3, vl0, vl1, vl2, vl3;
                    ldsm_x4t(vh0, vh1, vh2, vh3, a);
                    ldsm_x4t(vl0, vl1, vl2, vl3, a + 2 * (VL_OFF - VH_OFF));
                    float* o0 = o[2 * nfp];
                    float* o1 = o[2 * nfp + 1];
                    mma_bf16(o0[0], o0[1], o0[2], o0[3], ah0, ah1, ah2, ah3, vh0, vh1);
                    mma_bf16(o0[0], o0[1], o0[2], o0[3], al0, al1, al2, al3, vh0, vh1);
                    mma_bf16(o0[0], o0[1], o0[2], o0[3], ah0, ah1, ah2, ah3, vl0, vl1);
                    mma_bf16(o1[0], o1[1], o1[2], o1[3], ah0, ah1, ah2, ah3, vh2, vh3);
                    mma_bf16(o1[0], o1[1], o1[2], o1[3], al0, al1, al2, al3, vh2, vh3);
                    mma_bf16(o1[0], o1[1], o1[2], o1[3], ah0, ah1, ah2, ah3, vl2, vl3);
                }
            }
        }
    }

    l0 += __shfl_xor_sync(0xffffffffu, l0, 1);
    l0 += __shfl_xor_sync(0xffffffffu, l0, 2);
    l1 += __shfl_xor_sync(0xffffffffu, l1, 1);
    l1 += __shfl_xor_sync(0xffffffffu, l1, 2);
    const float inv0 = 1.f / l0;
    const float inv1 = 1.f / l1;

    // Epilogue: split to bf16 hi/lo planes.
    // Row stride in u32 = DMODEL/2; row+8 offset = 8*(DMODEL/2) = 4*DMODEL u32.
    const size_t row0 = (size_t)(b * SEQ + qblk * 128 + 16 * w + g);
    unsigned* obh = (unsigned*)(outh + row0 * DMODEL + h * DHEAD);
    unsigned* obl = (unsigned*)(outl + row0 * DMODEL + h * DHEAD);
    #pragma unroll
    for (int nf = 0; nf < 16; nf++) {
        const int ci = 4 * nf + q;                 // u32 index (col/2)
        float x0 = o[nf][0] * inv0, x1 = o[nf][1] * inv0;
        float y0 = o[nf][2] * inv1, y1 = o[nf][3] * inv1;
        __nv_bfloat162 xh = __floats2bfloat162_rn(x0, x1);
        __nv_bfloat162 yh = __floats2bfloat162_rn(y0, y1);
        __nv_bfloat162 xl = __floats2bfloat162_rn(x0 - __low2float(xh),
                                                  x1 - __high2float(xh));
        __nv_bfloat162 yl = __floats2bfloat162_rn(y0 - __low2float(yh),
                                                  y1 - __high2float(yh));
        obh[ci] = bf2u(xh);
        obl[ci] = bf2u(xl);
        obh[ci + 4 * DMODEL] = bf2u(yh);          // row + 8  (FIXED offset)
        obl[ci + 4 * DMODEL] = bf2u(yl);
    }
}

// ---------------------------------------------------------------------------
// kernel_launch
// ---------------------------------------------------------------------------
extern "C" void kernel_launch(void* const* d_in, const int* in_sizes, int n_in,
                              void* d_out, int out_size)
{
    const float* x     = (const float*)d_in[0];
    const float* W_qkv = (const float*)d_in[1];
    const float* b_qkv = (const float*)d_in[2];
    const float* W_out = (const float*)d_in[3];
    const float* b_out = (const float*)d_in[4];
    float* out = (float*)d_out;

    float *qkv;
    __nv_bfloat16 *xh, *xl, *wqh, *wql, *woh, *wol, *ath, *atl;
    cudaGetSymbolAddress((void**)&qkv, g_qkv);
    cudaGetSymbolAddress((void**)&xh,  g_xh);
    cudaGetSymbolAddress((void**)&xl,  g_xl);
    cudaGetSymbolAddress((void**)&wqh, g_wqkvth);
    cudaGetSymbolAddress((void**)&wql, g_wqkvtl);
    cudaGetSymbolAddress((void**)&woh, g_woutth);
    cudaGetSymbolAddress((void**)&wol, g_wouttl);
    cudaGetSymbolAddress((void**)&ath, g_attnh);
    cudaGetSymbolAddress((void**)&atl, g_attnl);

    cudaFuncSetAttribute(flash_attn_tc_kernel,
                         cudaFuncAttributeMaxDynamicSharedMemorySize,
                         ATT_SMEM_BYTES);
    cudaFuncSetAttribute(gemm_planes_bias_kernel,
                         cudaFuncAttributeMaxDynamicSharedMemorySize,
                         GEMM_SMEM_BYTES);

    // Prep: split x, transpose+split weights
    split_rm_kernel<<<(MTOT * DMODEL / 4 + 255) / 256, 256>>>(
        (const float4*)x, (uint2*)xh, (uint2*)xl, MTOT * DMODEL / 4);
    split_tr_kernel<<<dim3(DM3 / 32, DMODEL / 32), 256>>>(
        W_qkv, wqh, wql, DMODEL, DM3);
    split_tr_kernel<<<dim3(DMODEL / 32, DMODEL / 32), 256>>>(
        W_out, woh, wol, DMODEL, DMODEL);

    // 1) QKV GEMM
    gemm_planes_bias_kernel<<<dim3(DM3 / 128, MTOT / 128), 256, GEMM_SMEM_BYTES>>>(
        xh, xl, wqh, wql, b_qkv, qkv, MTOT, DM3, DMODEL);

    // 2) Flash attention -> bf16 hi/lo planes
    flash_attn_tc_kernel<<<dim3(16, NHEADS, BATCH), 256, ATT_SMEM_BYTES>>>(
        qkv, ath, atl);

    // 3) Output GEMM
    gemm_planes_bias_kernel<<<dim3(DMODEL / 128, MTOT / 128), 256, GEMM_SMEM_BYTES>>>(
        ath, atl, woh, wol, b_out, out, MTOT, DMODEL, DMODEL);
}